// round 8
// baseline (speedup 1.0000x reference)
#include <cuda_runtime.h>
#include <cuda_fp16.h>
#include <cstdint>

#define FDIM 128
#define MAX_NODES 100000
#define MAX_EDGES 1600000
#define SCAN_B 1024
#define MAX_SCAN_BLOCKS ((MAX_NODES + SCAN_B - 1) / SCAN_B)

// ---------------- scratch (device globals: allocation-free rule) ----------------
__device__ float g_bufA[(size_t)MAX_NODES * FDIM];
__device__ float g_bufB[(size_t)MAX_NODES * FDIM];
__device__ float g_isq[MAX_NODES];
__device__ int   g_cnt[MAX_NODES];
__device__ int   g_lpos[MAX_EDGES];
__device__ int   g_rowptr[MAX_NODES + 1];
__device__ int   g_partial[MAX_SCAN_BLOCKS];
__device__ int2  g_epack[MAX_EDGES];

// ---------------- CSR build ----------------
__global__ void zero_kernel(int* __restrict__ cnt, int n) {
    int i = blockIdx.x * blockDim.x + threadIdx.x;
    if (i < n) cnt[i] = 0;
}
__global__ void count_kernel(const int* __restrict__ dst, int* __restrict__ cnt,
                             int* __restrict__ lpos, int E) {
    int e = blockIdx.x * blockDim.x + threadIdx.x;
    if (e < E) lpos[e] = atomicAdd(&cnt[dst[e]], 1);
}
__global__ void isq_kernel(const int* __restrict__ cnt, float* __restrict__ isq, int n) {
    int i = blockIdx.x * blockDim.x + threadIdx.x;
    if (i < n) isq[i] = rsqrtf((float)(cnt[i] + 1));
}
__global__ void block_scan_kernel(const int* __restrict__ cnt, int* __restrict__ rowptr,
                                  int* __restrict__ partial, int n) {
    __shared__ int sh[SCAN_B];
    int i = blockIdx.x * SCAN_B + threadIdx.x;
    int v = (i < n) ? cnt[i] : 0;
    sh[threadIdx.x] = v;
    __syncthreads();
#pragma unroll
    for (int off = 1; off < SCAN_B; off <<= 1) {
        int t = (threadIdx.x >= off) ? sh[threadIdx.x - off] : 0;
        __syncthreads();
        sh[threadIdx.x] += t;
        __syncthreads();
    }
    if (i < n) rowptr[i] = sh[threadIdx.x] - v;
    if (threadIdx.x == SCAN_B - 1) partial[blockIdx.x] = sh[SCAN_B - 1];
}
__global__ void partial_scan_kernel(int* __restrict__ partial, int nb) {
    if (threadIdx.x == 0) {
        int run = 0;
        for (int b = 0; b < nb; ++b) { int v = partial[b]; partial[b] = run; run += v; }
        partial[nb] = run;
    }
}
__global__ void add_offsets_kernel(int* __restrict__ rowptr, const int* __restrict__ partial,
                                   int n, int nb) {
    int i = blockIdx.x * blockDim.x + threadIdx.x;
    if (i < n) rowptr[i] += partial[i / SCAN_B];
    if (i == 0) rowptr[n] = partial[nb];
}
__global__ void fill_kernel(const int* __restrict__ src, const int* __restrict__ dst,
                            const float* __restrict__ isq, const int* __restrict__ rowptr,
                            const int* __restrict__ lpos, int2* __restrict__ epack, int E) {
    int e = blockIdx.x * blockDim.x + threadIdx.x;
    if (e >= E) return;
    int s = src[e], d = dst[e];
    epack[rowptr[d] + lpos[e]] = make_int2(s, __float_as_int(isq[s] * isq[d]));
}

// ---------------- aggregation: warp per node, CSR gather ----------------
__global__ void agg_kernel(const float* __restrict__ t, const int* __restrict__ rowptr,
                           const int2* __restrict__ epack, const float* __restrict__ isq,
                           float* __restrict__ agg, int n) {
    int node = (blockIdx.x * blockDim.x + threadIdx.x) >> 5;
    if (node >= n) return;
    int lane = threadIdx.x & 31;
    int beg = rowptr[node], end = rowptr[node + 1];
    float s = isq[node], c = s * s;
    float4 acc = __ldg((const float4*)(t + (size_t)node * FDIM) + lane);
    acc.x *= c; acc.y *= c; acc.z *= c; acc.w *= c;
    for (int j = beg; j < end; ++j) {
        int2 p = __ldg(&epack[j]);
        float w = __int_as_float(p.y);
        float4 v = __ldg((const float4*)(t + (size_t)p.x * FDIM) + lane);
        acc.x += w * v.x; acc.y += w * v.y; acc.z += w * v.z; acc.w += w * v.w;
    }
    ((float4*)(agg + (size_t)node * FDIM))[lane] = acc;
}

// ---------------- fp16 mma helper ----------------
__device__ __forceinline__ void mma_16n8k16(float& c0, float& c1, float& c2, float& c3,
                                            uint32_t a0, uint32_t a1, uint32_t a2, uint32_t a3,
                                            uint32_t b0, uint32_t b1) {
    asm volatile(
        "mma.sync.aligned.m16n8k16.row.col.f32.f16.f16.f32 "
        "{%0,%1,%2,%3}, {%4,%5,%6,%7}, {%8,%9}, {%0,%1,%2,%3};"
        : "+f"(c0), "+f"(c1), "+f"(c2), "+f"(c3)
        : "r"(a0), "r"(a1), "r"(a2), "r"(a3), "r"(b0), "r"(b1));
}

// ---------------- tensor-core GEMM via mma.sync fp16 (fp32 accumulate) -------------
// C[M,N_OUT] = prologue(A)[M,128] @ W[128,N_OUT] (+ebias)
// Block: 256 thr = 8 warps (ROWG x COLG); warp tile = 16 rows x 64 cols.
// A staged as half [BM][AST], W staged TRANSPOSED as half [N_OUT][KS].
// AST = KS = 136 halves (272B row stride; 272 % 128 == 16 -> conflict-free frags).
template <int N_OUT, bool PRELU>
__global__ __launch_bounds__(256, 3)
void gemm_mma_kernel(const float* __restrict__ A, const float* __restrict__ W,
                     const float* __restrict__ pbias, const float* __restrict__ ebias,
                     float* __restrict__ C, int M) {
    constexpr int COLG = N_OUT / 64;
    constexpr int ROWG = 8 / COLG;
    constexpr int BM   = ROWG * 16;
    constexpr int AST  = 136;   // halves
    constexpr int KS   = 136;   // halves
    constexpr int NT   = 8;     // 8 n-tiles of 8 cols = 64 cols per warp

    extern __shared__ __half smem_h[];
    __half* As = smem_h;                    // [BM][AST]
    __half* Wt = smem_h + BM * AST;         // [N_OUT][KS]  (transposed W)

    int tid  = threadIdx.x;
    int wid  = tid >> 5;
    int lane = tid & 31;
    int g    = lane >> 2;                   // 0..7
    int t4   = lane & 3;                    // 0..3
    int wid_r = wid / COLG;
    int wid_c = wid % COLG;
    int row0 = blockIdx.x * BM;

    // ---- stage W transposed: W[k][col] -> Wt[col][k] ----
    for (int i = tid; i < 128 * (N_OUT / 4); i += 256) {
        int k  = i / (N_OUT / 4);
        int c4 = i % (N_OUT / 4);
        float4 v = ((const float4*)(W + (size_t)k * N_OUT))[c4];
        Wt[(c4 * 4 + 0) * KS + k] = __float2half_rn(v.x);
        Wt[(c4 * 4 + 1) * KS + k] = __float2half_rn(v.y);
        Wt[(c4 * 4 + 2) * KS + k] = __float2half_rn(v.z);
        Wt[(c4 * 4 + 3) * KS + k] = __float2half_rn(v.w);
    }
    // ---- stage A tile with fused prologue ----
    for (int i = tid; i < BM * 32; i += 256) {
        int r  = i >> 5;
        int c4 = i & 31;
        int gr = row0 + r;
        float4 v = make_float4(0.f, 0.f, 0.f, 0.f);
        if (gr < M) {
            v = ((const float4*)(A + (size_t)gr * FDIM))[c4];
            if (pbias) {
                float4 b = ((const float4*)pbias)[c4];
                v.x += b.x; v.y += b.y; v.z += b.z; v.w += b.w;
            }
            if (PRELU) {
                v.x = fmaxf(v.x, 0.f); v.y = fmaxf(v.y, 0.f);
                v.z = fmaxf(v.z, 0.f); v.w = fmaxf(v.w, 0.f);
            }
        }
        __half* p = As + r * AST + c4 * 4;
        *(half2*)(p)     = __floats2half2_rn(v.x, v.y);
        *(half2*)(p + 2) = __floats2half2_rn(v.z, v.w);
    }
    __syncthreads();

    // ---- accumulators: 16 rows x 64 cols per warp ----
    float acc[NT][4];
#pragma unroll
    for (int nt = 0; nt < NT; ++nt) {
        acc[nt][0] = 0.f; acc[nt][1] = 0.f; acc[nt][2] = 0.f; acc[nt][3] = 0.f;
    }

    const __half* arow_lo = As + (wid_r * 16 + g) * AST;
    const __half* arow_hi = arow_lo + 8 * AST;
    const int ncol0 = wid_c * 64;

#pragma unroll
    for (int ks = 0; ks < 8; ++ks) {
        int k0 = ks * 16 + 2 * t4;
        uint32_t a0 = *(const uint32_t*)(arow_lo + k0);
        uint32_t a1 = *(const uint32_t*)(arow_hi + k0);
        uint32_t a2 = *(const uint32_t*)(arow_lo + k0 + 8);
        uint32_t a3 = *(const uint32_t*)(arow_hi + k0 + 8);
        const __half* wb = Wt + (ncol0 + g) * KS + k0;
#pragma unroll
        for (int nt = 0; nt < NT; ++nt) {
            uint32_t b0 = *(const uint32_t*)(wb + nt * 8 * KS);
            uint32_t b1 = *(const uint32_t*)(wb + nt * 8 * KS + 8);
            mma_16n8k16(acc[nt][0], acc[nt][1], acc[nt][2], acc[nt][3],
                        a0, a1, a2, a3, b0, b1);
        }
    }

    // ---- epilogue: c0,c1 -> row g col 2*t4,2*t4+1; c2,c3 -> row g+8 ----
    int r_lo = row0 + wid_r * 16 + g;
    int r_hi = r_lo + 8;
#pragma unroll
    for (int nt = 0; nt < NT; ++nt) {
        int col = ncol0 + nt * 8 + 2 * t4;
        float e0 = 0.f, e1 = 0.f;
        if (ebias) { e0 = __ldg(&ebias[col]); e1 = __ldg(&ebias[col + 1]); }
        if (r_lo < M) {
            float2 o = make_float2(acc[nt][0] + e0, acc[nt][1] + e1);
            *(float2*)(C + (size_t)r_lo * N_OUT + col) = o;
        }
        if (r_hi < M) {
            float2 o = make_float2(acc[nt][2] + e0, acc[nt][3] + e1);
            *(float2*)(C + (size_t)r_hi * N_OUT + col) = o;
        }
    }
}

// ---------------- launch ----------------
extern "C" void kernel_launch(void* const* d_in, const int* in_sizes, int n_in,
                              void* d_out, int out_size) {
    const float* x   = (const float*)d_in[0];
    const int*   ei  = (const int*)d_in[1];     // int32 (JAX x64 disabled)
    const float* W1  = (const float*)d_in[2];
    const float* b1  = (const float*)d_in[3];
    const float* W2  = (const float*)d_in[4];
    const float* b2  = (const float*)d_in[5];
    const float* W3  = (const float*)d_in[6];
    const float* b3  = (const float*)d_in[7];
    const float* Wo  = (const float*)d_in[8];
    const float* bo  = (const float*)d_in[9];

    int n = in_sizes[0] / FDIM;
    int E = in_sizes[1] / 2;
    const int* src = ei;
    const int* dst = ei + E;

    float *bufA, *bufB, *isq;
    int *cnt, *lpos, *rowptr, *partial;
    int2* epack;
    cudaGetSymbolAddress((void**)&bufA,    g_bufA);
    cudaGetSymbolAddress((void**)&bufB,    g_bufB);
    cudaGetSymbolAddress((void**)&isq,     g_isq);
    cudaGetSymbolAddress((void**)&cnt,     g_cnt);
    cudaGetSymbolAddress((void**)&lpos,    g_lpos);
    cudaGetSymbolAddress((void**)&rowptr,  g_rowptr);
    cudaGetSymbolAddress((void**)&partial, g_partial);
    cudaGetSymbolAddress((void**)&epack,   g_epack);

    // smem: (BM*136 + N_OUT*136) halves
    const int SMEM128 = (64 * 136 + 128 * 136) * 2;   // 52,224 B
    const int SMEM64  = (128 * 136 + 64 * 136) * 2;   // 52,224 B
    cudaFuncSetAttribute(gemm_mma_kernel<128, false>, cudaFuncAttributeMaxDynamicSharedMemorySize, SMEM128);
    cudaFuncSetAttribute(gemm_mma_kernel<128, true>,  cudaFuncAttributeMaxDynamicSharedMemorySize, SMEM128);
    cudaFuncSetAttribute(gemm_mma_kernel<64, false>,  cudaFuncAttributeMaxDynamicSharedMemorySize, SMEM64);

    const int T = 256;
    int nb_nodes   = (n + T - 1) / T;
    int nb_edges   = (E + T - 1) / T;
    int nb_agg     = (int)(((long long)n * 32 + T - 1) / T);
    int nb_gemm128 = (n + 63) / 64;     // BM=64 for N_OUT=128
    int nb_gemm64  = (n + 127) / 128;   // BM=128 for N_OUT=64
    int nb_scan    = (n + SCAN_B - 1) / SCAN_B;

    // ---- CSR build + normalization ----
    zero_kernel<<<nb_nodes, T>>>(cnt, n);
    count_kernel<<<nb_edges, T>>>(dst, cnt, lpos, E);
    isq_kernel<<<nb_nodes, T>>>(cnt, isq, n);
    block_scan_kernel<<<nb_scan, SCAN_B>>>(cnt, rowptr, partial, n);
    partial_scan_kernel<<<1, 32>>>(partial, nb_scan);
    add_offsets_kernel<<<nb_nodes, T>>>(rowptr, partial, n, nb_scan);
    fill_kernel<<<nb_edges, T>>>(src, dst, isq, rowptr, lpos, epack, E);

    // ---- layer 1 ----
    gemm_mma_kernel<128, false><<<nb_gemm128, 256, SMEM128>>>(x, W1, nullptr, nullptr, bufA, n);
    agg_kernel<<<nb_agg, T>>>(bufA, rowptr, epack, isq, bufB, n);

    // ---- layer 2 ----
    gemm_mma_kernel<128, true><<<nb_gemm128, 256, SMEM128>>>(bufB, W2, b1, nullptr, bufA, n);
    agg_kernel<<<nb_agg, T>>>(bufA, rowptr, epack, isq, bufB, n);

    // ---- layer 3 ----
    gemm_mma_kernel<128, true><<<nb_gemm128, 256, SMEM128>>>(bufB, W3, b2, nullptr, bufA, n);
    agg_kernel<<<nb_agg, T>>>(bufA, rowptr, epack, isq, bufB, n);

    // ---- output ----
    gemm_mma_kernel<64, false><<<nb_gemm64, 256, SMEM64>>>(bufB, Wo, b3, bo, (float*)d_out, n);
}

// round 9
// speedup vs baseline: 1.7551x; 1.7551x over previous
#include <cuda_runtime.h>
#include <cuda_fp16.h>
#include <cstdint>

#define FDIM 128
#define MAX_NODES 100000
#define MAX_EDGES 1600000
#define SCAN_B 1024
#define MAX_SCAN_BLOCKS ((MAX_NODES + SCAN_B - 1) / SCAN_B)

// ---------------- scratch (device globals: allocation-free rule) ----------------
__device__ __align__(16) __half g_hX[(size_t)MAX_NODES * FDIM];
__device__ __align__(16) __half g_hA[(size_t)MAX_NODES * FDIM];
__device__ __align__(16) __half g_hB[(size_t)MAX_NODES * FDIM];
__device__ float g_isq[MAX_NODES];
__device__ int   g_cnt[MAX_NODES];
__device__ int   g_lpos[MAX_EDGES];
__device__ int   g_rowptr[MAX_NODES + 1];
__device__ int   g_partial[MAX_SCAN_BLOCKS + 1];
__device__ int2  g_epack[MAX_EDGES];
// pre-transposed, padded W images: [N_OUT][136] halves
__device__ __align__(16) __half g_wt1[128 * 136];
__device__ __align__(16) __half g_wt2[128 * 136];
__device__ __align__(16) __half g_wt3[128 * 136];
__device__ __align__(16) __half g_wto[64 * 136];

// ---------------- CSR build ----------------
__global__ void zero_kernel(int* __restrict__ cnt, int n) {
    int i = blockIdx.x * blockDim.x + threadIdx.x;
    if (i < n) cnt[i] = 0;
}
__global__ void count_kernel(const int* __restrict__ dst, int* __restrict__ cnt,
                             int* __restrict__ lpos, int E) {
    int e = blockIdx.x * blockDim.x + threadIdx.x;
    if (e < E) lpos[e] = atomicAdd(&cnt[dst[e]], 1);
}
__global__ void isq_kernel(const int* __restrict__ cnt, float* __restrict__ isq, int n) {
    int i = blockIdx.x * blockDim.x + threadIdx.x;
    if (i < n) isq[i] = rsqrtf((float)(cnt[i] + 1));
}
__global__ void block_scan_kernel(const int* __restrict__ cnt, int* __restrict__ rowptr,
                                  int* __restrict__ partial, int n) {
    __shared__ int sh[SCAN_B];
    int i = blockIdx.x * SCAN_B + threadIdx.x;
    int v = (i < n) ? cnt[i] : 0;
    sh[threadIdx.x] = v;
    __syncthreads();
#pragma unroll
    for (int off = 1; off < SCAN_B; off <<= 1) {
        int t = (threadIdx.x >= off) ? sh[threadIdx.x - off] : 0;
        __syncthreads();
        sh[threadIdx.x] += t;
        __syncthreads();
    }
    if (i < n) rowptr[i] = sh[threadIdx.x] - v;
    if (threadIdx.x == SCAN_B - 1) partial[blockIdx.x] = sh[SCAN_B - 1];
}
// warp shfl scan over <=128 partials (one warp)
__global__ void partial_scan_kernel(int* __restrict__ partial, int nb) {
    int lane = threadIdx.x;   // 32 threads
    int base = lane * 4;
    int v0 = (base + 0 < nb) ? partial[base + 0] : 0;
    int v1 = (base + 1 < nb) ? partial[base + 1] : 0;
    int v2 = (base + 2 < nb) ? partial[base + 2] : 0;
    int v3 = (base + 3 < nb) ? partial[base + 3] : 0;
    int tot = v0 + v1 + v2 + v3;
    int x = tot;
#pragma unroll
    for (int off = 1; off < 32; off <<= 1) {
        int y = __shfl_up_sync(0xFFFFFFFF, x, off);
        if (lane >= off) x += y;
    }
    int run = x - tot;   // exclusive
    if (base + 0 < nb) partial[base + 0] = run;            run += v0;
    if (base + 1 < nb) partial[base + 1] = run;            run += v1;
    if (base + 2 < nb) partial[base + 2] = run;            run += v2;
    if (base + 3 < nb) partial[base + 3] = run;
    if (lane == 31) partial[nb] = x;                       // grand total
}
__global__ void add_offsets_kernel(int* __restrict__ rowptr, const int* __restrict__ partial,
                                   int n, int nb) {
    int i = blockIdx.x * blockDim.x + threadIdx.x;
    if (i < n) rowptr[i] += partial[i / SCAN_B];
    if (i == 0) rowptr[n] = partial[nb];
}
__global__ void fill_kernel(const int* __restrict__ src, const int* __restrict__ dst,
                            const float* __restrict__ isq, const int* __restrict__ rowptr,
                            const int* __restrict__ lpos, int2* __restrict__ epack, int E) {
    int e = blockIdx.x * blockDim.x + threadIdx.x;
    if (e >= E) return;
    int s = src[e], d = dst[e];
    epack[rowptr[d] + lpos[e]] = make_int2(s, __float_as_int(isq[s] * isq[d]));
}

// ---------------- fp32 -> fp16 convert (layer-1 input) ----------------
__global__ void f2h_kernel(const float* __restrict__ x, __half* __restrict__ xh, int total4) {
    int i = blockIdx.x * blockDim.x + threadIdx.x;
    if (i >= total4) return;
    float4 v = ((const float4*)x)[i];
    uint2 o;
    *(half2*)&o.x = __floats2half2_rn(v.x, v.y);
    *(half2*)&o.y = __floats2half2_rn(v.z, v.w);
    ((uint2*)xh)[i] = o;
}

// ---------------- W prep: W[128][N] fp32 -> Wt[N][136] half ----------------
template <int N_OUT>
__global__ void prep_wt_kernel(const float* __restrict__ W, __half* __restrict__ wt) {
    int i = blockIdx.x * blockDim.x + threadIdx.x;
    if (i >= 128 * N_OUT) return;
    int k  = i / N_OUT;
    int nr = i % N_OUT;
    wt[nr * 136 + k] = __float2half_rn(W[i]);
}

// ---------------- aggregation: warp per node, half gather, fused bias(+relu) ------
template <bool RELU>
__global__ void agg_kernel(const __half* __restrict__ t, const int* __restrict__ rowptr,
                           const int2* __restrict__ epack, const float* __restrict__ isq,
                           const float* __restrict__ bias, __half* __restrict__ out, int n) {
    int node = (blockIdx.x * blockDim.x + threadIdx.x) >> 5;
    if (node >= n) return;
    int lane = threadIdx.x & 31;
    int beg = rowptr[node], end = rowptr[node + 1];
    float s = isq[node], c = s * s;

    uint2 raw = __ldg((const uint2*)(t + (size_t)node * FDIM) + lane);
    float2 f0 = __half22float2(*(half2*)&raw.x);
    float2 f1 = __half22float2(*(half2*)&raw.y);
    float4 acc = make_float4(c * f0.x, c * f0.y, c * f1.x, c * f1.y);

    for (int j = beg; j < end; ++j) {
        int2 p = __ldg(&epack[j]);
        float w = __int_as_float(p.y);
        uint2 r2 = __ldg((const uint2*)(t + (size_t)p.x * FDIM) + lane);
        float2 g0 = __half22float2(*(half2*)&r2.x);
        float2 g1 = __half22float2(*(half2*)&r2.y);
        acc.x += w * g0.x; acc.y += w * g0.y; acc.z += w * g1.x; acc.w += w * g1.y;
    }
    float4 b = __ldg((const float4*)bias + lane);
    acc.x += b.x; acc.y += b.y; acc.z += b.z; acc.w += b.w;
    if (RELU) {
        acc.x = fmaxf(acc.x, 0.f); acc.y = fmaxf(acc.y, 0.f);
        acc.z = fmaxf(acc.z, 0.f); acc.w = fmaxf(acc.w, 0.f);
    }
    uint2 o;
    *(half2*)&o.x = __floats2half2_rn(acc.x, acc.y);
    *(half2*)&o.y = __floats2half2_rn(acc.z, acc.w);
    ((uint2*)(out + (size_t)node * FDIM))[lane] = o;
}

// ---------------- fp16 mma helper ----------------
__device__ __forceinline__ void mma_16n8k16(float& c0, float& c1, float& c2, float& c3,
                                            uint32_t a0, uint32_t a1, uint32_t a2, uint32_t a3,
                                            uint32_t b0, uint32_t b1) {
    asm volatile(
        "mma.sync.aligned.m16n8k16.row.col.f32.f16.f16.f32 "
        "{%0,%1,%2,%3}, {%4,%5,%6,%7}, {%8,%9}, {%0,%1,%2,%3};"
        : "+f"(c0), "+f"(c1), "+f"(c2), "+f"(c3)
        : "r"(a0), "r"(a1), "r"(a2), "r"(a3), "r"(b0), "r"(b1));
}

// ---------------- GEMM: C = A(half)[M,128] @ W -> half C (or fp32 + ebias) --------
// A staged straight copy; Wt staged straight copy from pre-transposed image.
template <int N_OUT, bool OUT_FP32>
__global__ __launch_bounds__(256, 4)
void gemm_mma_kernel(const __half* __restrict__ A, const __half* __restrict__ Wimg,
                     const float* __restrict__ ebias, void* __restrict__ Cout, int M) {
    constexpr int COLG = N_OUT / 64;
    constexpr int ROWG = 8 / COLG;
    constexpr int BM   = ROWG * 16;
    constexpr int AST  = 136;   // halves
    constexpr int KS   = 136;   // halves
    constexpr int NT   = 8;

    extern __shared__ __half smem_h[];
    __half* As = smem_h;                    // [BM][AST]
    __half* Wt = smem_h + BM * AST;         // [N_OUT][KS]

    int tid  = threadIdx.x;
    int wid  = tid >> 5;
    int lane = tid & 31;
    int g    = lane >> 2;
    int t4   = lane & 3;
    int wid_r = wid / COLG;
    int wid_c = wid % COLG;
    int row0 = blockIdx.x * BM;

    // Wt: straight uint4 copy (N_OUT*136 halves = N_OUT*17 uint4)
    for (int i = tid; i < N_OUT * 17; i += 256)
        ((uint4*)Wt)[i] = ((const uint4*)Wimg)[i];
    // A: straight uint2 copy per 4 halves
    for (int i = tid; i < BM * 32; i += 256) {
        int r  = i >> 5;
        int c4 = i & 31;
        int gr = row0 + r;
        uint2 v = make_uint2(0u, 0u);
        if (gr < M) v = ((const uint2*)(A + (size_t)gr * FDIM))[c4];
        *(uint2*)(As + r * AST + c4 * 4) = v;
    }
    __syncthreads();

    float acc[NT][4];
#pragma unroll
    for (int nt = 0; nt < NT; ++nt) {
        acc[nt][0] = 0.f; acc[nt][1] = 0.f; acc[nt][2] = 0.f; acc[nt][3] = 0.f;
    }

    const __half* arow_lo = As + (wid_r * 16 + g) * AST;
    const __half* arow_hi = arow_lo + 8 * AST;
    const int ncol0 = wid_c * 64;

#pragma unroll
    for (int ks = 0; ks < 8; ++ks) {
        int k0 = ks * 16 + 2 * t4;
        uint32_t a0 = *(const uint32_t*)(arow_lo + k0);
        uint32_t a1 = *(const uint32_t*)(arow_hi + k0);
        uint32_t a2 = *(const uint32_t*)(arow_lo + k0 + 8);
        uint32_t a3 = *(const uint32_t*)(arow_hi + k0 + 8);
        const __half* wb = Wt + (ncol0 + g) * KS + k0;
#pragma unroll
        for (int nt = 0; nt < NT; ++nt) {
            uint32_t b0 = *(const uint32_t*)(wb + nt * 8 * KS);
            uint32_t b1 = *(const uint32_t*)(wb + nt * 8 * KS + 8);
            mma_16n8k16(acc[nt][0], acc[nt][1], acc[nt][2], acc[nt][3],
                        a0, a1, a2, a3, b0, b1);
        }
    }

    int r_lo = row0 + wid_r * 16 + g;
    int r_hi = r_lo + 8;
#pragma unroll
    for (int nt = 0; nt < NT; ++nt) {
        int col = ncol0 + nt * 8 + 2 * t4;
        if (OUT_FP32) {
            float* C = (float*)Cout;
            float e0 = __ldg(&ebias[col]), e1 = __ldg(&ebias[col + 1]);
            if (r_lo < M)
                *(float2*)(C + (size_t)r_lo * N_OUT + col) = make_float2(acc[nt][0] + e0, acc[nt][1] + e1);
            if (r_hi < M)
                *(float2*)(C + (size_t)r_hi * N_OUT + col) = make_float2(acc[nt][2] + e0, acc[nt][3] + e1);
        } else {
            __half* C = (__half*)Cout;
            if (r_lo < M)
                *(half2*)(C + (size_t)r_lo * N_OUT + col) = __floats2half2_rn(acc[nt][0], acc[nt][1]);
            if (r_hi < M)
                *(half2*)(C + (size_t)r_hi * N_OUT + col) = __floats2half2_rn(acc[nt][2], acc[nt][3]);
        }
    }
}

// ---------------- launch ----------------
extern "C" void kernel_launch(void* const* d_in, const int* in_sizes, int n_in,
                              void* d_out, int out_size) {
    const float* x   = (const float*)d_in[0];
    const int*   ei  = (const int*)d_in[1];     // int32 (JAX x64 disabled)
    const float* W1  = (const float*)d_in[2];
    const float* b1  = (const float*)d_in[3];
    const float* W2  = (const float*)d_in[4];
    const float* b2  = (const float*)d_in[5];
    const float* W3  = (const float*)d_in[6];
    const float* b3  = (const float*)d_in[7];
    const float* Wo  = (const float*)d_in[8];
    const float* bo  = (const float*)d_in[9];

    int n = in_sizes[0] / FDIM;
    int E = in_sizes[1] / 2;
    const int* src = ei;
    const int* dst = ei + E;

    __half *hX, *hA, *hB, *wt1, *wt2, *wt3, *wto;
    float *isq;
    int *cnt, *lpos, *rowptr, *partial;
    int2* epack;
    cudaGetSymbolAddress((void**)&hX,      g_hX);
    cudaGetSymbolAddress((void**)&hA,      g_hA);
    cudaGetSymbolAddress((void**)&hB,      g_hB);
    cudaGetSymbolAddress((void**)&isq,     g_isq);
    cudaGetSymbolAddress((void**)&cnt,     g_cnt);
    cudaGetSymbolAddress((void**)&lpos,    g_lpos);
    cudaGetSymbolAddress((void**)&rowptr,  g_rowptr);
    cudaGetSymbolAddress((void**)&partial, g_partial);
    cudaGetSymbolAddress((void**)&epack,   g_epack);
    cudaGetSymbolAddress((void**)&wt1,     g_wt1);
    cudaGetSymbolAddress((void**)&wt2,     g_wt2);
    cudaGetSymbolAddress((void**)&wt3,     g_wt3);
    cudaGetSymbolAddress((void**)&wto,     g_wto);

    const int SMEM128 = (64 * 136 + 128 * 136) * 2;   // 52,224 B
    const int SMEM64  = (128 * 136 + 64 * 136) * 2;   // 52,224 B
    cudaFuncSetAttribute(gemm_mma_kernel<128, false>, cudaFuncAttributeMaxDynamicSharedMemorySize, SMEM128);
    cudaFuncSetAttribute(gemm_mma_kernel<64, true>,   cudaFuncAttributeMaxDynamicSharedMemorySize, SMEM64);

    const int T = 256;
    int nb_nodes   = (n + T - 1) / T;
    int nb_edges   = (E + T - 1) / T;
    int nb_agg     = (int)(((long long)n * 32 + T - 1) / T);
    int nb_gemm128 = (n + 63) / 64;
    int nb_gemm64  = (n + 127) / 128;
    int nb_scan    = (n + SCAN_B - 1) / SCAN_B;
    int nb_f2h     = (n * 32 + T - 1) / T;

    // ---- CSR build + normalization + conversions ----
    zero_kernel<<<nb_nodes, T>>>(cnt, n);
    count_kernel<<<nb_edges, T>>>(dst, cnt, lpos, E);
    isq_kernel<<<nb_nodes, T>>>(cnt, isq, n);
    block_scan_kernel<<<nb_scan, SCAN_B>>>(cnt, rowptr, partial, n);
    partial_scan_kernel<<<1, 32>>>(partial, nb_scan);
    add_offsets_kernel<<<nb_nodes, T>>>(rowptr, partial, n, nb_scan);
    fill_kernel<<<nb_edges, T>>>(src, dst, isq, rowptr, lpos, epack, E);
    f2h_kernel<<<nb_f2h, T>>>(x, hX, n * 32);
    prep_wt_kernel<128><<<64, 256>>>(W1, wt1);
    prep_wt_kernel<128><<<64, 256>>>(W2, wt2);
    prep_wt_kernel<128><<<64, 256>>>(W3, wt3);
    prep_wt_kernel<64><<<32, 256>>>(Wo, wto);

    // ---- layer 1: h1 = relu(agg(xh @ W1) + b1) ----
    gemm_mma_kernel<128, false><<<nb_gemm128, 256, SMEM128>>>(hX, wt1, nullptr, hA, n);
    agg_kernel<true><<<nb_agg, T>>>(hA, rowptr, epack, isq, b1, hB, n);

    // ---- layer 2 ----
    gemm_mma_kernel<128, false><<<nb_gemm128, 256, SMEM128>>>(hB, wt2, nullptr, hA, n);
    agg_kernel<true><<<nb_agg, T>>>(hA, rowptr, epack, isq, b2, hB, n);

    // ---- layer 3 (no relu) ----
    gemm_mma_kernel<128, false><<<nb_gemm128, 256, SMEM128>>>(hB, wt3, nullptr, hA, n);
    agg_kernel<false><<<nb_agg, T>>>(hA, rowptr, epack, isq, b3, hB, n);

    // ---- output: out = h3 @ Wout + bout (fp32) ----
    gemm_mma_kernel<64, true><<<nb_gemm64, 256, SMEM64>>>(hB, wto, bo, (float*)d_out, n);
}

// round 10
// speedup vs baseline: 1.9683x; 1.1215x over previous
#include <cuda_runtime.h>
#include <cuda_fp16.h>
#include <cstdint>

#define FDIM 128
#define MAX_NODES 100000
#define MAX_EDGES 1600000
#define SCAN_B 1024
#define MAX_SCAN_BLOCKS ((MAX_NODES + SCAN_B - 1) / SCAN_B)

// ---------------- scratch (device globals: allocation-free rule) ----------------
__device__ __align__(16) __half g_hA[(size_t)MAX_NODES * FDIM];
__device__ __align__(16) __half g_hB[(size_t)MAX_NODES * FDIM];
__device__ float g_isq[MAX_NODES];
__device__ int   g_cnt[MAX_NODES];
__device__ int   g_lpos[MAX_EDGES];
__device__ int   g_rowptr[MAX_NODES + 1];
__device__ int   g_partial[MAX_SCAN_BLOCKS + 1];
__device__ int2  g_epack[MAX_EDGES];
// pre-transposed, padded W images: [N_OUT][136] halves
__device__ __align__(16) __half g_wt1[128 * 136];
__device__ __align__(16) __half g_wt2[128 * 136];
__device__ __align__(16) __half g_wtf[64 * 136];   // fused W3@Wout, transposed
__device__ float g_bf[64];                          // fused b3@Wout + bout

// ---------------- CSR build ----------------
__global__ void zero_kernel(int* __restrict__ cnt, int n) {
    int i = blockIdx.x * blockDim.x + threadIdx.x;
    if (i < n) cnt[i] = 0;
}
__global__ void count_kernel(const int* __restrict__ dst, int* __restrict__ cnt,
                             int* __restrict__ lpos, int E) {
    int e = blockIdx.x * blockDim.x + threadIdx.x;
    if (e < E) lpos[e] = atomicAdd(&cnt[dst[e]], 1);
}
__global__ void isq_kernel(const int* __restrict__ cnt, float* __restrict__ isq, int n) {
    int i = blockIdx.x * blockDim.x + threadIdx.x;
    if (i < n) isq[i] = rsqrtf((float)(cnt[i] + 1));
}
__global__ void block_scan_kernel(const int* __restrict__ cnt, int* __restrict__ rowptr,
                                  int* __restrict__ partial, int n) {
    __shared__ int sh[SCAN_B];
    int i = blockIdx.x * SCAN_B + threadIdx.x;
    int v = (i < n) ? cnt[i] : 0;
    sh[threadIdx.x] = v;
    __syncthreads();
#pragma unroll
    for (int off = 1; off < SCAN_B; off <<= 1) {
        int t = (threadIdx.x >= off) ? sh[threadIdx.x - off] : 0;
        __syncthreads();
        sh[threadIdx.x] += t;
        __syncthreads();
    }
    if (i < n) rowptr[i] = sh[threadIdx.x] - v;
    if (threadIdx.x == SCAN_B - 1) partial[blockIdx.x] = sh[SCAN_B - 1];
}
__global__ void partial_scan_kernel(int* __restrict__ partial, int nb) {
    int lane = threadIdx.x;   // 32 threads
    int base = lane * 4;
    int v0 = (base + 0 < nb) ? partial[base + 0] : 0;
    int v1 = (base + 1 < nb) ? partial[base + 1] : 0;
    int v2 = (base + 2 < nb) ? partial[base + 2] : 0;
    int v3 = (base + 3 < nb) ? partial[base + 3] : 0;
    int tot = v0 + v1 + v2 + v3;
    int x = tot;
#pragma unroll
    for (int off = 1; off < 32; off <<= 1) {
        int y = __shfl_up_sync(0xFFFFFFFF, x, off);
        if (lane >= off) x += y;
    }
    int run = x - tot;
    if (base + 0 < nb) partial[base + 0] = run;            run += v0;
    if (base + 1 < nb) partial[base + 1] = run;            run += v1;
    if (base + 2 < nb) partial[base + 2] = run;            run += v2;
    if (base + 3 < nb) partial[base + 3] = run;
    if (lane == 31) partial[nb] = x;
}
__global__ void add_offsets_kernel(int* __restrict__ rowptr, const int* __restrict__ partial,
                                   int n, int nb) {
    int i = blockIdx.x * blockDim.x + threadIdx.x;
    if (i < n) rowptr[i] += partial[i / SCAN_B];
    if (i == 0) rowptr[n] = partial[nb];
}
__global__ void fill_kernel(const int* __restrict__ src, const int* __restrict__ dst,
                            const float* __restrict__ isq, const int* __restrict__ rowptr,
                            const int* __restrict__ lpos, int2* __restrict__ epack, int E) {
    int e = blockIdx.x * blockDim.x + threadIdx.x;
    if (e >= E) return;
    int s = src[e], d = dst[e];
    epack[rowptr[d] + lpos[e]] = make_int2(s, __float_as_int(isq[s] * isq[d]));
}

// ---------------- W prep ----------------
template <int N_OUT>
__global__ void prep_wt_kernel(const float* __restrict__ W, __half* __restrict__ wt) {
    int i = blockIdx.x * blockDim.x + threadIdx.x;
    if (i >= 128 * N_OUT) return;
    int k  = i / N_OUT;
    int nr = i % N_OUT;
    wt[nr * 136 + k] = __float2half_rn(W[i]);
}
// fused: Wf = W3 @ Wout (fp32), transposed half image; bf = b3 @ Wout + bout
__global__ void fuse_w_kernel(const float* __restrict__ W3, const float* __restrict__ Wo,
                              const float* __restrict__ b3, const float* __restrict__ bo,
                              __half* __restrict__ wtf, float* __restrict__ bf) {
    int i = blockIdx.x * blockDim.x + threadIdx.x;
    if (i < 128 * 64) {
        int r = i >> 6;      // k (row of W3')
        int c = i & 63;      // out col
        float s = 0.f;
#pragma unroll 8
        for (int j = 0; j < 128; ++j) s += W3[r * 128 + j] * Wo[j * 64 + c];
        wtf[c * 136 + r] = __float2half_rn(s);
    }
    if (i < 64) {
        float s = bo[i];
#pragma unroll 8
        for (int j = 0; j < 128; ++j) s += b3[j] * Wo[j * 64 + i];
        bf[i] = s;
    }
}

// ---------------- aggregation: warp per node, half gather, fused bias+relu --------
template <bool RELU>
__global__ void agg_kernel(const __half* __restrict__ t, const int* __restrict__ rowptr,
                           const int2* __restrict__ epack, const float* __restrict__ isq,
                           const float* __restrict__ bias, __half* __restrict__ out, int n) {
    int node = (blockIdx.x * blockDim.x + threadIdx.x) >> 5;
    if (node >= n) return;
    int lane = threadIdx.x & 31;
    int beg = rowptr[node], end = rowptr[node + 1];
    float s = isq[node], c = s * s;

    uint2 raw = __ldg((const uint2*)(t + (size_t)node * FDIM) + lane);
    float2 f0 = __half22float2(*(half2*)&raw.x);
    float2 f1 = __half22float2(*(half2*)&raw.y);
    float4 acc = make_float4(c * f0.x, c * f0.y, c * f1.x, c * f1.y);

    for (int j = beg; j < end; ++j) {
        int2 p = __ldg(&epack[j]);
        float w = __int_as_float(p.y);
        uint2 r2 = __ldg((const uint2*)(t + (size_t)p.x * FDIM) + lane);
        float2 g0 = __half22float2(*(half2*)&r2.x);
        float2 g1 = __half22float2(*(half2*)&r2.y);
        acc.x += w * g0.x; acc.y += w * g0.y; acc.z += w * g1.x; acc.w += w * g1.y;
    }
    float4 b = __ldg((const float4*)bias + lane);
    acc.x += b.x; acc.y += b.y; acc.z += b.z; acc.w += b.w;
    if (RELU) {
        acc.x = fmaxf(acc.x, 0.f); acc.y = fmaxf(acc.y, 0.f);
        acc.z = fmaxf(acc.z, 0.f); acc.w = fmaxf(acc.w, 0.f);
    }
    uint2 o;
    *(half2*)&o.x = __floats2half2_rn(acc.x, acc.y);
    *(half2*)&o.y = __floats2half2_rn(acc.z, acc.w);
    ((uint2*)(out + (size_t)node * FDIM))[lane] = o;
}

// final agg: 64 features, fp32 output with fused bias (writes d_out directly)
__global__ void agg64_kernel(const __half* __restrict__ t, const int* __restrict__ rowptr,
                             const int2* __restrict__ epack, const float* __restrict__ isq,
                             const float* __restrict__ bias, float* __restrict__ out, int n) {
    int node = (blockIdx.x * blockDim.x + threadIdx.x) >> 5;
    if (node >= n) return;
    int lane = threadIdx.x & 31;
    int beg = rowptr[node], end = rowptr[node + 1];
    float s = isq[node], c = s * s;

    uint32_t raw = __ldg((const uint32_t*)(t + (size_t)node * 64) + lane);
    float2 f = __half22float2(*(half2*)&raw);
    float2 acc = make_float2(c * f.x, c * f.y);

    for (int j = beg; j < end; ++j) {
        int2 p = __ldg(&epack[j]);
        float w = __int_as_float(p.y);
        uint32_t r2 = __ldg((const uint32_t*)(t + (size_t)p.x * 64) + lane);
        float2 g = __half22float2(*(half2*)&r2);
        acc.x += w * g.x; acc.y += w * g.y;
    }
    float2 b = __ldg((const float2*)bias + lane);
    acc.x += b.x; acc.y += b.y;
    ((float2*)(out + (size_t)node * 64))[lane] = acc;
}

// ---------------- fp16 mma helper ----------------
__device__ __forceinline__ void mma_16n8k16(float& c0, float& c1, float& c2, float& c3,
                                            uint32_t a0, uint32_t a1, uint32_t a2, uint32_t a3,
                                            uint32_t b0, uint32_t b1) {
    asm volatile(
        "mma.sync.aligned.m16n8k16.row.col.f32.f16.f16.f32 "
        "{%0,%1,%2,%3}, {%4,%5,%6,%7}, {%8,%9}, {%0,%1,%2,%3};"
        : "+f"(c0), "+f"(c1), "+f"(c2), "+f"(c3)
        : "r"(a0), "r"(a1), "r"(a2), "r"(a3), "r"(b0), "r"(b1));
}

// ---------------- GEMM: C(half) = A[M,128] @ W ; A fp32 or fp16 ------------------
template <int N_OUT, bool A_FP32>
__global__ __launch_bounds__(256, 4)
void gemm_mma_kernel(const void* __restrict__ Ain, const __half* __restrict__ Wimg,
                     __half* __restrict__ C, int M) {
    constexpr int COLG = N_OUT / 64;
    constexpr int ROWG = 8 / COLG;
    constexpr int BM   = ROWG * 16;
    constexpr int AST  = 136;
    constexpr int KS   = 136;
    constexpr int NT   = 8;

    extern __shared__ __half smem_h[];
    __half* As = smem_h;                    // [BM][AST]
    __half* Wt = smem_h + BM * AST;         // [N_OUT][KS]

    int tid  = threadIdx.x;
    int wid  = tid >> 5;
    int lane = tid & 31;
    int g    = lane >> 2;
    int t4   = lane & 3;
    int wid_r = wid / COLG;
    int wid_c = wid % COLG;
    int row0 = blockIdx.x * BM;

    for (int i = tid; i < N_OUT * 17; i += 256)
        ((uint4*)Wt)[i] = ((const uint4*)Wimg)[i];
    for (int i = tid; i < BM * 32; i += 256) {
        int r  = i >> 5;
        int c4 = i & 31;
        int gr = row0 + r;
        uint2 v = make_uint2(0u, 0u);
        if (gr < M) {
            if (A_FP32) {
                float4 f = ((const float4*)((const float*)Ain + (size_t)gr * FDIM))[c4];
                *(half2*)&v.x = __floats2half2_rn(f.x, f.y);
                *(half2*)&v.y = __floats2half2_rn(f.z, f.w);
            } else {
                v = ((const uint2*)((const __half*)Ain + (size_t)gr * FDIM))[c4];
            }
        }
        *(uint2*)(As + r * AST + c4 * 4) = v;
    }
    __syncthreads();

    float acc[NT][4];
#pragma unroll
    for (int nt = 0; nt < NT; ++nt) {
        acc[nt][0] = 0.f; acc[nt][1] = 0.f; acc[nt][2] = 0.f; acc[nt][3] = 0.f;
    }

    const __half* arow_lo = As + (wid_r * 16 + g) * AST;
    const __half* arow_hi = arow_lo + 8 * AST;
    const int ncol0 = wid_c * 64;

#pragma unroll
    for (int ks = 0; ks < 8; ++ks) {
        int k0 = ks * 16 + 2 * t4;
        uint32_t a0 = *(const uint32_t*)(arow_lo + k0);
        uint32_t a1 = *(const uint32_t*)(arow_hi + k0);
        uint32_t a2 = *(const uint32_t*)(arow_lo + k0 + 8);
        uint32_t a3 = *(const uint32_t*)(arow_hi + k0 + 8);
        const __half* wb = Wt + (ncol0 + g) * KS + k0;
#pragma unroll
        for (int nt = 0; nt < NT; ++nt) {
            uint32_t b0 = *(const uint32_t*)(wb + nt * 8 * KS);
            uint32_t b1 = *(const uint32_t*)(wb + nt * 8 * KS + 8);
            mma_16n8k16(acc[nt][0], acc[nt][1], acc[nt][2], acc[nt][3],
                        a0, a1, a2, a3, b0, b1);
        }
    }

    int r_lo = row0 + wid_r * 16 + g;
    int r_hi = r_lo + 8;
#pragma unroll
    for (int nt = 0; nt < NT; ++nt) {
        int col = ncol0 + nt * 8 + 2 * t4;
        if (r_lo < M)
            *(half2*)(C + (size_t)r_lo * N_OUT + col) = __floats2half2_rn(acc[nt][0], acc[nt][1]);
        if (r_hi < M)
            *(half2*)(C + (size_t)r_hi * N_OUT + col) = __floats2half2_rn(acc[nt][2], acc[nt][3]);
    }
}

// ---------------- launch ----------------
extern "C" void kernel_launch(void* const* d_in, const int* in_sizes, int n_in,
                              void* d_out, int out_size) {
    const float* x   = (const float*)d_in[0];
    const int*   ei  = (const int*)d_in[1];     // int32 (JAX x64 disabled)
    const float* W1  = (const float*)d_in[2];
    const float* b1  = (const float*)d_in[3];
    const float* W2  = (const float*)d_in[4];
    const float* b2  = (const float*)d_in[5];
    const float* W3  = (const float*)d_in[6];
    const float* b3  = (const float*)d_in[7];
    const float* Wo  = (const float*)d_in[8];
    const float* bo  = (const float*)d_in[9];

    int n = in_sizes[0] / FDIM;
    int E = in_sizes[1] / 2;
    const int* src = ei;
    const int* dst = ei + E;

    __half *hA, *hB, *wt1, *wt2, *wtf;
    float *isq, *bf;
    int *cnt, *lpos, *rowptr, *partial;
    int2* epack;
    cudaGetSymbolAddress((void**)&hA,      g_hA);
    cudaGetSymbolAddress((void**)&hB,      g_hB);
    cudaGetSymbolAddress((void**)&isq,     g_isq);
    cudaGetSymbolAddress((void**)&cnt,     g_cnt);
    cudaGetSymbolAddress((void**)&lpos,    g_lpos);
    cudaGetSymbolAddress((void**)&rowptr,  g_rowptr);
    cudaGetSymbolAddress((void**)&partial, g_partial);
    cudaGetSymbolAddress((void**)&epack,   g_epack);
    cudaGetSymbolAddress((void**)&wt1,     g_wt1);
    cudaGetSymbolAddress((void**)&wt2,     g_wt2);
    cudaGetSymbolAddress((void**)&wtf,     g_wtf);
    cudaGetSymbolAddress((void**)&bf,      g_bf);

    const int SMEM = (64 * 136 + 128 * 136) * 2;   // 52,224 B (same for both shapes)
    cudaFuncSetAttribute(gemm_mma_kernel<128, true>,  cudaFuncAttributeMaxDynamicSharedMemorySize, SMEM);
    cudaFuncSetAttribute(gemm_mma_kernel<128, false>, cudaFuncAttributeMaxDynamicSharedMemorySize, SMEM);
    cudaFuncSetAttribute(gemm_mma_kernel<64, false>,  cudaFuncAttributeMaxDynamicSharedMemorySize, SMEM);

    const int T = 256;
    int nb_nodes   = (n + T - 1) / T;
    int nb_edges   = (E + T - 1) / T;
    int nb_agg     = (int)(((long long)n * 32 + T - 1) / T);
    int nb_gemm128 = (n + 63) / 64;
    int nb_gemm64  = (n + 127) / 128;
    int nb_scan    = (n + SCAN_B - 1) / SCAN_B;

    // ---- CSR build + normalization + W prep ----
    zero_kernel<<<nb_nodes, T>>>(cnt, n);
    count_kernel<<<nb_edges, T>>>(dst, cnt, lpos, E);
    isq_kernel<<<nb_nodes, T>>>(cnt, isq, n);
    block_scan_kernel<<<nb_scan, SCAN_B>>>(cnt, rowptr, partial, n);
    partial_scan_kernel<<<1, 32>>>(partial, nb_scan);
    add_offsets_kernel<<<nb_nodes, T>>>(rowptr, partial, n, nb_scan);
    fill_kernel<<<nb_edges, T>>>(src, dst, isq, rowptr, lpos, epack, E);
    prep_wt_kernel<128><<<64, 256>>>(W1, wt1);
    prep_wt_kernel<128><<<64, 256>>>(W2, wt2);
    fuse_w_kernel<<<32, 256>>>(W3, Wo, b3, bo, wtf, bf);

    // ---- layer 1: h1 = relu(agg(x @ W1) + b1)  (fp32 A, converted in staging) ----
    gemm_mma_kernel<128, true><<<nb_gemm128, 256, SMEM>>>(x, wt1, hA, n);
    agg_kernel<true><<<nb_agg, T>>>(hA, rowptr, epack, isq, b1, hB, n);

    // ---- layer 2 ----
    gemm_mma_kernel<128, false><<<nb_gemm128, 256, SMEM>>>(hB, wt2, hA, n);
    agg_kernel<true><<<nb_agg, T>>>(hA, rowptr, epack, isq, b2, hB, n);

    // ---- layer 3 + output fused: out = agg(h2 @ (W3@Wout)) + (b3@Wout + bout) ----
    gemm_mma_kernel<64, false><<<nb_gemm64, 256, SMEM>>>(hB, wtf, hA, n);
    agg64_kernel<<<nb_agg, T>>>(hA, rowptr, epack, isq, bf, (float*)d_out, n);
}

// round 11
// speedup vs baseline: 1.9795x; 1.0057x over previous
#include <cuda_runtime.h>
#include <cuda_fp16.h>
#include <cstdint>

#define FDIM 128
#define MAX_NODES 100000
#define MAX_EDGES 1600000
#define SCAN_B 1024
#define MAX_SCAN_BLOCKS ((MAX_NODES + SCAN_B - 1) / SCAN_B)

// ---------------- scratch (device globals: allocation-free rule) ----------------
__device__ __align__(16) __half g_hA[(size_t)MAX_NODES * FDIM];
__device__ __align__(16) __half g_hB[(size_t)MAX_NODES * FDIM];
__device__ float g_isq[MAX_NODES];
__device__ int   g_cnt[MAX_NODES];
__device__ int   g_lpos[MAX_EDGES];
__device__ int   g_rowptr[MAX_NODES + 1];
__device__ int   g_partial[MAX_SCAN_BLOCKS + 1];
__device__ int2  g_epack[MAX_EDGES];
// pre-transposed, padded W images: [N_OUT][136] halves
__device__ __align__(16) __half g_wt1[128 * 136];
__device__ __align__(16) __half g_wt2[128 * 136];
__device__ __align__(16) __half g_wtf[64 * 136];   // fused W3@Wout, transposed
__device__ float g_bf[64];                          // fused b3@Wout + bout

// ---------------- CSR build ----------------
__global__ void zero_kernel(int* __restrict__ cnt, int n) {
    int i = blockIdx.x * blockDim.x + threadIdx.x;
    if (i < n) cnt[i] = 0;
}
__global__ void count_kernel(const int* __restrict__ dst, int* __restrict__ cnt,
                             int* __restrict__ lpos, int E) {
    int e = blockIdx.x * blockDim.x + threadIdx.x;
    if (e < E) lpos[e] = atomicAdd(&cnt[dst[e]], 1);
}
__global__ void isq_kernel(const int* __restrict__ cnt, float* __restrict__ isq, int n) {
    int i = blockIdx.x * blockDim.x + threadIdx.x;
    if (i < n) isq[i] = rsqrtf((float)(cnt[i] + 1));
}
__global__ void block_scan_kernel(const int* __restrict__ cnt, int* __restrict__ rowptr,
                                  int* __restrict__ partial, int n) {
    __shared__ int sh[SCAN_B];
    int i = blockIdx.x * SCAN_B + threadIdx.x;
    int v = (i < n) ? cnt[i] : 0;
    sh[threadIdx.x] = v;
    __syncthreads();
#pragma unroll
    for (int off = 1; off < SCAN_B; off <<= 1) {
        int t = (threadIdx.x >= off) ? sh[threadIdx.x - off] : 0;
        __syncthreads();
        sh[threadIdx.x] += t;
        __syncthreads();
    }
    if (i < n) rowptr[i] = sh[threadIdx.x] - v;
    if (threadIdx.x == SCAN_B - 1) partial[blockIdx.x] = sh[SCAN_B - 1];
}
__global__ void partial_scan_kernel(int* __restrict__ partial, int nb) {
    int lane = threadIdx.x;   // 32 threads
    int base = lane * 4;
    int v0 = (base + 0 < nb) ? partial[base + 0] : 0;
    int v1 = (base + 1 < nb) ? partial[base + 1] : 0;
    int v2 = (base + 2 < nb) ? partial[base + 2] : 0;
    int v3 = (base + 3 < nb) ? partial[base + 3] : 0;
    int tot = v0 + v1 + v2 + v3;
    int x = tot;
#pragma unroll
    for (int off = 1; off < 32; off <<= 1) {
        int y = __shfl_up_sync(0xFFFFFFFF, x, off);
        if (lane >= off) x += y;
    }
    int run = x - tot;
    if (base + 0 < nb) partial[base + 0] = run;            run += v0;
    if (base + 1 < nb) partial[base + 1] = run;            run += v1;
    if (base + 2 < nb) partial[base + 2] = run;            run += v2;
    if (base + 3 < nb) partial[base + 3] = run;
    if (lane == 31) partial[nb] = x;
}
__global__ void add_offsets_kernel(int* __restrict__ rowptr, const int* __restrict__ partial,
                                   int n, int nb) {
    int i = blockIdx.x * blockDim.x + threadIdx.x;
    if (i < n) rowptr[i] += partial[i / SCAN_B];
    if (i == 0) rowptr[n] = partial[nb];
}
__global__ void fill_kernel(const int* __restrict__ src, const int* __restrict__ dst,
                            const float* __restrict__ isq, const int* __restrict__ rowptr,
                            const int* __restrict__ lpos, int2* __restrict__ epack, int E) {
    int e = blockIdx.x * blockDim.x + threadIdx.x;
    if (e >= E) return;
    int s = src[e], d = dst[e];
    epack[rowptr[d] + lpos[e]] = make_int2(s, __float_as_int(isq[s] * isq[d]));
}

// ---------------- W prep ----------------
template <int N_OUT>
__global__ void prep_wt_kernel(const float* __restrict__ W, __half* __restrict__ wt) {
    int i = blockIdx.x * blockDim.x + threadIdx.x;
    if (i >= 128 * N_OUT) return;
    int k  = i / N_OUT;
    int nr = i % N_OUT;
    wt[nr * 136 + k] = __float2half_rn(W[i]);
}
// fused: Wf = W3 @ Wout (fp32), transposed half image; bf = b3 @ Wout + bout
__global__ void fuse_w_kernel(const float* __restrict__ W3, const float* __restrict__ Wo,
                              const float* __restrict__ b3, const float* __restrict__ bo,
                              __half* __restrict__ wtf, float* __restrict__ bf) {
    int i = blockIdx.x * blockDim.x + threadIdx.x;
    if (i < 128 * 64) {
        int r = i >> 6;      // k (row of W3')
        int c = i & 63;      // out col
        float s = 0.f;
#pragma unroll 8
        for (int j = 0; j < 128; ++j) s += W3[r * 128 + j] * Wo[j * 64 + c];
        wtf[c * 136 + r] = __float2half_rn(s);
    }
    if (i < 64) {
        float s = bo[i];
#pragma unroll 8
        for (int j = 0; j < 128; ++j) s += b3[j] * Wo[j * 64 + i];
        bf[i] = s;
    }
}

// ---------------- aggregation: warp per node, half gather, fused bias+relu --------
template <bool RELU>
__global__ void agg_kernel(const __half* __restrict__ t, const int* __restrict__ rowptr,
                           const int2* __restrict__ epack, const float* __restrict__ isq,
                           const float* __restrict__ bias, __half* __restrict__ out, int n) {
    int node = (blockIdx.x * blockDim.x + threadIdx.x) >> 5;
    if (node >= n) return;
    int lane = threadIdx.x & 31;
    int beg = rowptr[node], end = rowptr[node + 1];
    float s = isq[node], c = s * s;

    uint2 raw = __ldg((const uint2*)(t + (size_t)node * FDIM) + lane);
    float2 f0 = __half22float2(*(half2*)&raw.x);
    float2 f1 = __half22float2(*(half2*)&raw.y);
    float4 acc = make_float4(c * f0.x, c * f0.y, c * f1.x, c * f1.y);

    for (int j = beg; j < end; ++j) {
        int2 p = __ldg(&epack[j]);
        float w = __int_as_float(p.y);
        uint2 r2 = __ldg((const uint2*)(t + (size_t)p.x * FDIM) + lane);
        float2 g0 = __half22float2(*(half2*)&r2.x);
        float2 g1 = __half22float2(*(half2*)&r2.y);
        acc.x += w * g0.x; acc.y += w * g0.y; acc.z += w * g1.x; acc.w += w * g1.y;
    }
    float4 b = __ldg((const float4*)bias + lane);
    acc.x += b.x; acc.y += b.y; acc.z += b.z; acc.w += b.w;
    if (RELU) {
        acc.x = fmaxf(acc.x, 0.f); acc.y = fmaxf(acc.y, 0.f);
        acc.z = fmaxf(acc.z, 0.f); acc.w = fmaxf(acc.w, 0.f);
    }
    uint2 o;
    *(half2*)&o.x = __floats2half2_rn(acc.x, acc.y);
    *(half2*)&o.y = __floats2half2_rn(acc.z, acc.w);
    ((uint2*)(out + (size_t)node * FDIM))[lane] = o;
}

// final agg: 64 features, fp32 output with fused bias (writes d_out directly)
__global__ void agg64_kernel(const __half* __restrict__ t, const int* __restrict__ rowptr,
                             const int2* __restrict__ epack, const float* __restrict__ isq,
                             const float* __restrict__ bias, float* __restrict__ out, int n) {
    int node = (blockIdx.x * blockDim.x + threadIdx.x) >> 5;
    if (node >= n) return;
    int lane = threadIdx.x & 31;
    int beg = rowptr[node], end = rowptr[node + 1];
    float s = isq[node], c = s * s;

    uint32_t raw = __ldg((const uint32_t*)(t + (size_t)node * 64) + lane);
    float2 f = __half22float2(*(half2*)&raw);
    float2 acc = make_float2(c * f.x, c * f.y);

    for (int j = beg; j < end; ++j) {
        int2 p = __ldg(&epack[j]);
        float w = __int_as_float(p.y);
        uint32_t r2 = __ldg((const uint32_t*)(t + (size_t)p.x * 64) + lane);
        float2 g = __half22float2(*(half2*)&r2);
        acc.x += w * g.x; acc.y += w * g.y;
    }
    float2 b = __ldg((const float2*)bias + lane);
    acc.x += b.x; acc.y += b.y;
    ((float2*)(out + (size_t)node * 64))[lane] = acc;
}

// ---------------- fp16 mma helper ----------------
__device__ __forceinline__ void mma_16n8k16(float& c0, float& c1, float& c2, float& c3,
                                            uint32_t a0, uint32_t a1, uint32_t a2, uint32_t a3,
                                            uint32_t b0, uint32_t b1) {
    asm volatile(
        "mma.sync.aligned.m16n8k16.row.col.f32.f16.f16.f32 "
        "{%0,%1,%2,%3}, {%4,%5,%6,%7}, {%8,%9}, {%0,%1,%2,%3};"
        : "+f"(c0), "+f"(c1), "+f"(c2), "+f"(c3)
        : "r"(a0), "r"(a1), "r"(a2), "r"(a3), "r"(b0), "r"(b1));
}

// ---------------- GEMM: C(half) = A[M,128] @ W ; A fp32 or fp16 ------------------
template <int N_OUT, bool A_FP32>
__global__ __launch_bounds__(256, 4)
void gemm_mma_kernel(const void* __restrict__ Ain, const __half* __restrict__ Wimg,
                     __half* __restrict__ C, int M) {
    constexpr int COLG = N_OUT / 64;
    constexpr int ROWG = 8 / COLG;
    constexpr int BM   = ROWG * 16;
    constexpr int AST  = 136;
    constexpr int KS   = 136;
    constexpr int NT   = 8;

    extern __shared__ __half smem_h[];
    __half* As = smem_h;                    // [BM][AST]
    __half* Wt = smem_h + BM * AST;         // [N_OUT][KS]

    int tid  = threadIdx.x;
    int wid  = tid >> 5;
    int lane = tid & 31;
    int g    = lane >> 2;
    int t4   = lane & 3;
    int wid_r = wid / COLG;
    int wid_c = wid % COLG;
    int row0 = blockIdx.x * BM;

    for (int i = tid; i < N_OUT * 17; i += 256)
        ((uint4*)Wt)[i] = ((const uint4*)Wimg)[i];
    for (int i = tid; i < BM * 32; i += 256) {
        int r  = i >> 5;
        int c4 = i & 31;
        int gr = row0 + r;
        uint2 v = make_uint2(0u, 0u);
        if (gr < M) {
            if (A_FP32) {
                float4 f = ((const float4*)((const float*)Ain + (size_t)gr * FDIM))[c4];
                *(half2*)&v.x = __floats2half2_rn(f.x, f.y);
                *(half2*)&v.y = __floats2half2_rn(f.z, f.w);
            } else {
                v = ((const uint2*)((const __half*)Ain + (size_t)gr * FDIM))[c4];
            }
        }
        *(uint2*)(As + r * AST + c4 * 4) = v;
    }
    __syncthreads();

    float acc[NT][4];
#pragma unroll
    for (int nt = 0; nt < NT; ++nt) {
        acc[nt][0] = 0.f; acc[nt][1] = 0.f; acc[nt][2] = 0.f; acc[nt][3] = 0.f;
    }

    const __half* arow_lo = As + (wid_r * 16 + g) * AST;
    const __half* arow_hi = arow_lo + 8 * AST;
    const int ncol0 = wid_c * 64;

#pragma unroll
    for (int ks = 0; ks < 8; ++ks) {
        int k0 = ks * 16 + 2 * t4;
        uint32_t a0 = *(const uint32_t*)(arow_lo + k0);
        uint32_t a1 = *(const uint32_t*)(arow_hi + k0);
        uint32_t a2 = *(const uint32_t*)(arow_lo + k0 + 8);
        uint32_t a3 = *(const uint32_t*)(arow_hi + k0 + 8);
        const __half* wb = Wt + (ncol0 + g) * KS + k0;
#pragma unroll
        for (int nt = 0; nt < NT; ++nt) {
            uint32_t b0 = *(const uint32_t*)(wb + nt * 8 * KS);
            uint32_t b1 = *(const uint32_t*)(wb + nt * 8 * KS + 8);
            mma_16n8k16(acc[nt][0], acc[nt][1], acc[nt][2], acc[nt][3],
                        a0, a1, a2, a3, b0, b1);
        }
    }

    int r_lo = row0 + wid_r * 16 + g;
    int r_hi = r_lo + 8;
#pragma unroll
    for (int nt = 0; nt < NT; ++nt) {
        int col = ncol0 + nt * 8 + 2 * t4;
        if (r_lo < M)
            *(half2*)(C + (size_t)r_lo * N_OUT + col) = __floats2half2_rn(acc[nt][0], acc[nt][1]);
        if (r_hi < M)
            *(half2*)(C + (size_t)r_hi * N_OUT + col) = __floats2half2_rn(acc[nt][2], acc[nt][3]);
    }
}

// ---------------- launch ----------------
extern "C" void kernel_launch(void* const* d_in, const int* in_sizes, int n_in,
                              void* d_out, int out_size) {
    const float* x   = (const float*)d_in[0];
    const int*   ei  = (const int*)d_in[1];     // int32 (JAX x64 disabled)
    const float* W1  = (const float*)d_in[2];
    const float* b1  = (const float*)d_in[3];
    const float* W2  = (const float*)d_in[4];
    const float* b2  = (const float*)d_in[5];
    const float* W3  = (const float*)d_in[6];
    const float* b3  = (const float*)d_in[7];
    const float* Wo  = (const float*)d_in[8];
    const float* bo  = (const float*)d_in[9];

    int n = in_sizes[0] / FDIM;
    int E = in_sizes[1] / 2;
    const int* src = ei;
    const int* dst = ei + E;

    __half *hA, *hB, *wt1, *wt2, *wtf;
    float *isq, *bf;
    int *cnt, *lpos, *rowptr, *partial;
    int2* epack;
    cudaGetSymbolAddress((void**)&hA,      g_hA);
    cudaGetSymbolAddress((void**)&hB,      g_hB);
    cudaGetSymbolAddress((void**)&isq,     g_isq);
    cudaGetSymbolAddress((void**)&cnt,     g_cnt);
    cudaGetSymbolAddress((void**)&lpos,    g_lpos);
    cudaGetSymbolAddress((void**)&rowptr,  g_rowptr);
    cudaGetSymbolAddress((void**)&partial, g_partial);
    cudaGetSymbolAddress((void**)&epack,   g_epack);
    cudaGetSymbolAddress((void**)&wt1,     g_wt1);
    cudaGetSymbolAddress((void**)&wt2,     g_wt2);
    cudaGetSymbolAddress((void**)&wtf,     g_wtf);
    cudaGetSymbolAddress((void**)&bf,      g_bf);

    const int SMEM = (64 * 136 + 128 * 136) * 2;   // 52,224 B (same for both shapes)
    cudaFuncSetAttribute(gemm_mma_kernel<128, true>,  cudaFuncAttributeMaxDynamicSharedMemorySize, SMEM);
    cudaFuncSetAttribute(gemm_mma_kernel<128, false>, cudaFuncAttributeMaxDynamicSharedMemorySize, SMEM);
    cudaFuncSetAttribute(gemm_mma_kernel<64, false>,  cudaFuncAttributeMaxDynamicSharedMemorySize, SMEM);

    const int T = 256;
    int nb_nodes   = (n + T - 1) / T;
    int nb_edges   = (E + T - 1) / T;
    int nb_agg     = (int)(((long long)n * 32 + T - 1) / T);
    int nb_gemm128 = (n + 63) / 64;
    int nb_gemm64  = (n + 127) / 128;
    int nb_scan    = (n + SCAN_B - 1) / SCAN_B;

    // ---- CSR build + normalization + W prep ----
    zero_kernel<<<nb_nodes, T>>>(cnt, n);
    count_kernel<<<nb_edges, T>>>(dst, cnt, lpos, E);
    isq_kernel<<<nb_nodes, T>>>(cnt, isq, n);
    block_scan_kernel<<<nb_scan, SCAN_B>>>(cnt, rowptr, partial, n);
    partial_scan_kernel<<<1, 32>>>(partial, nb_scan);
    add_offsets_kernel<<<nb_nodes, T>>>(rowptr, partial, n, nb_scan);
    fill_kernel<<<nb_edges, T>>>(src, dst, isq, rowptr, lpos, epack, E);
    prep_wt_kernel<128><<<64, 256>>>(W1, wt1);
    prep_wt_kernel<128><<<64, 256>>>(W2, wt2);
    fuse_w_kernel<<<32, 256>>>(W3, Wo, b3, bo, wtf, bf);

    // ---- layer 1: h1 = relu(agg(x @ W1) + b1)  (fp32 A, converted in staging) ----
    gemm_mma_kernel<128, true><<<nb_gemm128, 256, SMEM>>>(x, wt1, hA, n);
    agg_kernel<true><<<nb_agg, T>>>(hA, rowptr, epack, isq, b1, hB, n);

    // ---- layer 2 ----
    gemm_mma_kernel<128, false><<<nb_gemm128, 256, SMEM>>>(hB, wt2, hA, n);
    agg_kernel<true><<<nb_agg, T>>>(hA, rowptr, epack, isq, b2, hB, n);

    // ---- layer 3 + output fused: out = agg(h2 @ (W3@Wout)) + (b3@Wout + bout) ----
    gemm_mma_kernel<64, false><<<nb_gemm64, 256, SMEM>>>(hB, wtf, hA, n);
    agg64_kernel<<<nb_agg, T>>>(hA, rowptr, epack, isq, bf, (float*)d_out, n);
}